// round 1
// baseline (speedup 1.0000x reference)
#include <cuda_runtime.h>

// YoloLayer2: x (16, 3*85, 76, 76) f32 -> out (16, 3, 76, 76, 85) f32
// Per (b,a): transpose [85 x 5776] -> [5776 x 85] with elementwise transforms:
//   attr 0: (w + sigmoid(v)) / 76
//   attr 1: (h + sigmoid(v)) / 76
//   attr 2: exp(v) * anchor_w[a] / 608
//   attr 3: exp(v) * anchor_h[a] / 608
//   attr>=4: sigmoid(v)

#define NUM_B 16
#define NUM_A 3
#define DIM_H 76
#define DIM_W 76
#define HW (DIM_H * DIM_W)       // 5776
#define ATTR 85
#define TILE_P 128                // pixels per block
#define NTHREADS 128

__device__ __forceinline__ float fsigmoid(float v) {
    // fast sigmoid: 1 / (1 + exp(-v))
    return __fdividef(1.0f, 1.0f + __expf(-v));
}

__global__ __launch_bounds__(NTHREADS)
void yolo_kernel(const float* __restrict__ x, float* __restrict__ out) {
    __shared__ float sm[TILE_P * ATTR];   // 43520 bytes

    const int tile = blockIdx.x;          // pixel tile within (b,a)
    const int ba   = blockIdx.y;          // b*3 + a, 0..47
    const int a    = ba % NUM_A;

    // anchor_w = masked[0:3] = {10,13,16}; anchor_h = masked[1:4] = {13,16,30}
    const float AW[3] = {10.0f, 13.0f, 16.0f};
    const float AH[3] = {13.0f, 16.0f, 30.0f};
    const float sw = AW[a] * (1.0f / 608.0f);
    const float sh = AH[a] * (1.0f / 608.0f);

    const int p0     = tile * TILE_P;
    const int nvalid = min(TILE_P, HW - p0);
    const int tid    = threadIdx.x;

    const float* __restrict__ base_in = x + (size_t)ba * ATTR * HW + p0;

    if (tid < nvalid) {
        const int p  = p0 + tid;
        const int hj = p / DIM_W;
        const int wi = p - hj * DIM_W;
        const float fw = (float)wi;
        const float fh = (float)hj;
        const float inv76 = 1.0f / 76.0f;

        float* __restrict__ row = sm + tid * ATTR;

        // attrs 0..3 (special)
        {
            float v0 = base_in[0 * HW + tid];
            float v1 = base_in[1 * HW + tid];
            float v2 = base_in[2 * HW + tid];
            float v3 = base_in[3 * HW + tid];
            row[0] = (fw + fsigmoid(v0)) * inv76;
            row[1] = (fh + fsigmoid(v1)) * inv76;
            row[2] = __expf(v2) * sw;
            row[3] = __expf(v3) * sh;
        }
        // attrs 4..84: sigmoid
        #pragma unroll 9
        for (int attr = 4; attr < ATTR; attr++) {
            float v = base_in[attr * HW + tid];
            row[attr] = fsigmoid(v);
        }
    }
    __syncthreads();

    // Coalesced flat write: nvalid*85 contiguous floats; nvalid is always a
    // multiple of 4 here (128 or 16), so total is a multiple of 4.
    float* __restrict__ base_out = out + (size_t)(ba * HW + p0) * ATTR;
    const int total4 = (nvalid * ATTR) >> 2;
    const float4* __restrict__ s4 = (const float4*)sm;
    float4* __restrict__ o4 = (float4*)base_out;
    for (int k = tid; k < total4; k += NTHREADS) {
        o4[k] = s4[k];
    }
}

extern "C" void kernel_launch(void* const* d_in, const int* in_sizes, int n_in,
                              void* d_out, int out_size) {
    const float* x = (const float*)d_in[0];
    float* out = (float*)d_out;
    dim3 grid((HW + TILE_P - 1) / TILE_P, NUM_B * NUM_A);  // (46, 48)
    yolo_kernel<<<grid, NTHREADS>>>(x, out);
}

// round 2
// speedup vs baseline: 1.1956x; 1.1956x over previous
#include <cuda_runtime.h>

// YoloLayer2: x (16, 3*85, 76, 76) f32 -> out (16, 3, 76, 76, 85) f32
// Per (b,a): transpose [85 x 5776] -> [5776 x 85] with elementwise transforms:
//   attr 0: (wi + sigmoid(v)) / 76
//   attr 1: (hj + sigmoid(v)) / 76
//   attr 2: exp(v) * anchor_w[a] / 608
//   attr 3: exp(v) * anchor_h[a] / 608
//   attr>=4: sigmoid(v)

#define NUM_B 16
#define NUM_A 3
#define DIM_H 76
#define DIM_W 76
#define HW (DIM_H * DIM_W)        // 5776
#define ATTR 85
#define TILE_P 64                 // pixels per block (smem = 64*85*4 = 21760 B)
#define V4 (TILE_P / 4)           // 16 float4 per attr row
#define NTHREADS 256

__device__ __forceinline__ float fsigmoid(float v) {
    return __fdividef(1.0f, 1.0f + __expf(-v));
}

__global__ __launch_bounds__(NTHREADS)
void yolo_kernel(const float* __restrict__ x, float* __restrict__ out) {
    __shared__ float sm[TILE_P * ATTR];   // 21760 bytes

    const int tile = blockIdx.x;          // pixel tile within (b,a)
    const int ba   = blockIdx.y;          // b*3 + a, 0..47
    const int a    = ba % NUM_A;

    // anchor_w = masked[0:3] = {10,13,16}; anchor_h = masked[1:4] = {13,16,30}
    const float AW[3] = {10.0f, 13.0f, 16.0f};
    const float AH[3] = {13.0f, 16.0f, 30.0f};
    const float sw = AW[a] * (1.0f / 608.0f);
    const float sh = AH[a] * (1.0f / 608.0f);

    const int p0     = tile * TILE_P;
    const int nvalid = min(TILE_P, HW - p0);   // 64, or 16 on the last tile
    const int tid    = threadIdx.x;

    const float* __restrict__ base_in = x + (size_t)ba * ATTR * HW + p0;

    // Element-parallel compute: ATTR * V4 = 1360 float4 elements across 256
    // threads. Loads are independent (high MLP) and coalesced per attr row.
    for (int idx = tid; idx < ATTR * V4; idx += NTHREADS) {
        const int attr = idx >> 4;        // idx / 16
        const int pl   = (idx & 15) << 2; // local pixel (multiple of 4)
        if (pl >= nvalid) continue;

        float4 v = *(const float4*)(base_in + attr * HW + pl);
        float vv[4] = {v.x, v.y, v.z, v.w};
        float r[4];

        if (attr >= 4) {
            #pragma unroll
            for (int k = 0; k < 4; k++) r[k] = fsigmoid(vv[k]);
        } else if (attr == 0) {
            #pragma unroll
            for (int k = 0; k < 4; k++) {
                const int p  = p0 + pl + k;
                const int wi = p % DIM_W;
                r[k] = ((float)wi + fsigmoid(vv[k])) * (1.0f / 76.0f);
            }
        } else if (attr == 1) {
            #pragma unroll
            for (int k = 0; k < 4; k++) {
                const int p  = p0 + pl + k;
                const int hj = p / DIM_W;
                r[k] = ((float)hj + fsigmoid(vv[k])) * (1.0f / 76.0f);
            }
        } else if (attr == 2) {
            #pragma unroll
            for (int k = 0; k < 4; k++) r[k] = __expf(vv[k]) * sw;
        } else { // attr == 3
            #pragma unroll
            for (int k = 0; k < 4; k++) r[k] = __expf(vv[k]) * sh;
        }

        // Transposed smem store: stride 85 between pixels -> conflict-free
        float* __restrict__ row = sm + pl * ATTR + attr;
        #pragma unroll
        for (int k = 0; k < 4; k++) row[k * ATTR] = r[k];
    }
    __syncthreads();

    // Coalesced flat write of nvalid*85 contiguous floats (multiple of 4).
    float* __restrict__ base_out = out + (size_t)(ba * HW + p0) * ATTR;
    const int total4 = (nvalid * ATTR) >> 2;
    const float4* __restrict__ s4 = (const float4*)sm;
    float4* __restrict__ o4 = (float4*)base_out;
    for (int k = tid; k < total4; k += NTHREADS) {
        o4[k] = s4[k];
    }
}

extern "C" void kernel_launch(void* const* d_in, const int* in_sizes, int n_in,
                              void* d_out, int out_size) {
    const float* x = (const float*)d_in[0];
    float* out = (float*)d_out;
    dim3 grid((HW + TILE_P - 1) / TILE_P, NUM_B * NUM_A);  // (91, 48)
    yolo_kernel<<<grid, NTHREADS>>>(x, out);
}

// round 3
// speedup vs baseline: 1.1966x; 1.0008x over previous
#include <cuda_runtime.h>

// YoloLayer2: x (16, 3*85, 76, 76) f32 -> out (16, 3, 76, 76, 85) f32
// Per (b,a): transpose [85 x 5776] -> [5776 x 85] with elementwise transforms:
//   attr 0: (wi + sigmoid(v)) / 76
//   attr 1: (hj + sigmoid(v)) / 76
//   attr 2: exp(v) * anchor_w[a] / 608
//   attr 3: exp(v) * anchor_h[a] / 608
//   attr>=4: sigmoid(v)

#define NUM_B 16
#define NUM_A 3
#define DIM_H 76
#define DIM_W 76
#define HW (DIM_H * DIM_W)        // 5776
#define ATTR 85
#define TILE_P 64                 // pixels per block (smem = 64*85*4 = 21760 B)
#define V4 (TILE_P / 4)           // 16 float4 per attr row
#define NTHREADS 256

// sigmoid(v) = 0.5*tanh(v/2) + 0.5  -- single MUFU (tanh.approx) + FMAs
__device__ __forceinline__ float fsigmoid(float v) {
    float t;
    asm("tanh.approx.f32 %0, %1;" : "=f"(t) : "f"(v * 0.5f));
    return fmaf(t, 0.5f, 0.5f);
}

__global__ __launch_bounds__(NTHREADS)
void yolo_kernel(const float* __restrict__ x, float* __restrict__ out) {
    __shared__ float sm[TILE_P * ATTR];   // 21760 bytes

    const int tile = blockIdx.x;          // pixel tile within (b,a)
    const int ba   = blockIdx.y;          // b*3 + a, 0..47
    const int a    = ba % NUM_A;

    // anchor_w = masked[0:3] = {10,13,16}; anchor_h = masked[1:4] = {13,16,30}
    const float AW[3] = {10.0f, 13.0f, 16.0f};
    const float AH[3] = {13.0f, 16.0f, 30.0f};
    const float sw = AW[a] * (1.0f / 608.0f);
    const float sh = AH[a] * (1.0f / 608.0f);

    const int p0     = tile * TILE_P;
    const int nvalid = min(TILE_P, HW - p0);   // 64, or 16 on the last tile
    const int tid    = threadIdx.x;

    const float* __restrict__ base_in = x + (size_t)ba * ATTR * HW + p0;

    // Element-parallel compute: ATTR * V4 = 1360 float4 elements across 256
    // threads. Loads are independent (high MLP) and coalesced per attr row.
    for (int idx = tid; idx < ATTR * V4; idx += NTHREADS) {
        const int attr = idx >> 4;        // idx / 16
        const int pl   = (idx & 15) << 2; // local pixel (multiple of 4)
        if (pl >= nvalid) continue;

        float4 v = *(const float4*)(base_in + attr * HW + pl);
        float vv[4] = {v.x, v.y, v.z, v.w};
        float r[4];

        if (attr >= 4) {
            #pragma unroll
            for (int k = 0; k < 4; k++) r[k] = fsigmoid(vv[k]);
        } else if (attr == 0) {
            #pragma unroll
            for (int k = 0; k < 4; k++) {
                const int p  = p0 + pl + k;
                const int wi = p % DIM_W;
                r[k] = ((float)wi + fsigmoid(vv[k])) * (1.0f / 76.0f);
            }
        } else if (attr == 1) {
            #pragma unroll
            for (int k = 0; k < 4; k++) {
                const int p  = p0 + pl + k;
                const int hj = p / DIM_W;
                r[k] = ((float)hj + fsigmoid(vv[k])) * (1.0f / 76.0f);
            }
        } else if (attr == 2) {
            #pragma unroll
            for (int k = 0; k < 4; k++) r[k] = __expf(vv[k]) * sw;
        } else { // attr == 3
            #pragma unroll
            for (int k = 0; k < 4; k++) r[k] = __expf(vv[k]) * sh;
        }

        // Transposed smem store: stride 85 between pixels
        float* __restrict__ row = sm + pl * ATTR + attr;
        #pragma unroll
        for (int k = 0; k < 4; k++) row[k * ATTR] = r[k];
    }
    __syncthreads();

    // Coalesced flat write of nvalid*85 contiguous floats (multiple of 4).
    float* __restrict__ base_out = out + (size_t)(ba * HW + p0) * ATTR;
    const int total4 = (nvalid * ATTR) >> 2;
    const float4* __restrict__ s4 = (const float4*)sm;
    float4* __restrict__ o4 = (float4*)base_out;
    for (int k = tid; k < total4; k += NTHREADS) {
        o4[k] = s4[k];
    }
}

extern "C" void kernel_launch(void* const* d_in, const int* in_sizes, int n_in,
                              void* d_out, int out_size) {
    const float* x = (const float*)d_in[0];
    float* out = (float*)d_out;
    dim3 grid((HW + TILE_P - 1) / TILE_P, NUM_B * NUM_A);  // (91, 48)
    yolo_kernel<<<grid, NTHREADS>>>(x, out);
}